// round 10
// baseline (speedup 1.0000x reference)
#include <cuda_runtime.h>
#include <cuda_bf16.h>
#include <cstdint>

#define HDIM 1024
#define VDIM 128
#define NS   7          // K-splits: 3 chunks of 128 + 4 chunks of 160
#define NT   40         // 20 row-tiles x 2 col-halves

typedef unsigned long long ull;

// Split-K partials as (even-k, odd-k) float pairs; reduced+exp'd results
__device__ __align__(16) ull   g_Ep[NS * 2048 * VDIM];   // 14.7 MB
__device__ __align__(16) ull   g_Dp[NS * 512 * VDIM];    // 3.7 MB
__device__ __align__(16) float g_E[2048 * VDIM];         // exp(enc@W^T)
__device__ __align__(16) float g_D[512 * VDIM];          // exp(dec@W^T + b)

__device__ __forceinline__ ull fma2(ull a, ull b, ull c) {
    ull d;
    asm("fma.rn.f32x2 %0, %1, %2, %3;" : "=l"(d) : "l"(a), "l"(b), "l"(c));
    return d;
}

#define A_STR 36   // floats; 144B rows: float4 staging, reads 2-addr broadcast
#define W_STR 34   // floats; 136B rows: float2 staging, read banks 2*col_t distinct

// ---------------------------------------------------------------------------
// Split-K GEMM. Grid 280, 512 threads, 2 CTAs/SM -> 32 warps/SM (8/SMSP).
// Tile 128 rows x 64 cols; thread tile 4 rows x 4 cols (= 8192 outputs: FULL
// tile coverage, fixing round 9's half-tile bug). K in f32x2 lanes.
// Per warp per kk-pair: 8 LDS.64 + 16 FFMA2 -> fma-bound at 8 warps/SMSP.
// row_slot = warp*2 + (lane>>4) in [0,32); rows = row_slot + 32i (i<4).
// col_t = lane&15; cols = c0 + col_t + 16j (j<4).
// ---------------------------------------------------------------------------
__global__ __launch_bounds__(512, 2) void joint_gemm(
    const float* __restrict__ enc, const float* __restrict__ dec,
    const float* __restrict__ Wt)
{
    __shared__ __align__(16) float As[128 * A_STR];  // 18 KB
    __shared__ __align__(16) float Ws[64 * W_STR];   // 8.5 KB

    // bid remap: v<120 -> small chunks (s=0..2, K=128); v>=120 -> big (s=3..6, K=160).
    const int v = blockIdx.x;
    int s, tile;
    if (v < 120) { s = v / 40;          tile = v - s * 40; }
    else         { int w = v - 120; s = 3 + w / 40; tile = w - (s - 3) * 40; }
    const int iters = (s < 3) ? 4 : 5;
    const int k_lo  = (s < 3) ? s * 128 : 384 + (s - 3) * 160;

    const int rt = tile >> 1, ch = tile & 1;
    const bool is_dec = (rt >= 16);
    const float* A = is_dec ? dec : enc;
    const int row0 = (is_dec ? rt - 16 : rt) * 128;
    const int c0   = ch * 64;
    ull* Cp = is_dec ? (g_Dp + s * 512 * VDIM) : (g_Ep + s * 2048 * VDIM);

    const int tid      = threadIdx.x;
    const int lane     = tid & 31;
    const int warp     = tid >> 5;                  // 0..15
    const int row_slot = warp * 2 + (lane >> 4);    // 0..31
    const int col_t    = lane & 15;

    // Staging: A = 1024 float4 slots (2/thread), W = 1024 float2 slots (2/thread)
    const int a_r  = tid >> 3;           // 0..63; +64 second step
    const int a_k4 = (tid & 7) << 2;
    const int w_c  = tid >> 4;           // 0..31; +32 second step
    const int w_kp = (tid & 15) << 1;

    ull acc[4][4];
    #pragma unroll
    for (int i = 0; i < 4; i++)
        #pragma unroll
        for (int j = 0; j < 4; j++) acc[i][j] = 0ull;

    for (int it = 0; it < iters; it++) {
        const int k0 = k_lo + it * 32;
        float4 aReg[2];
        float2 wReg[2];
        #pragma unroll
        for (int st = 0; st < 2; st++)
            aReg[st] = *(const float4*)(A + (long)(row0 + a_r + st * 64) * HDIM + k0 + a_k4);
        #pragma unroll
        for (int st = 0; st < 2; st++)
            wReg[st] = *(const float2*)(Wt + (long)(c0 + w_c + st * 32) * HDIM + k0 + w_kp);

        __syncthreads();                  // previous compute done
        #pragma unroll
        for (int st = 0; st < 2; st++)
            *(float4*)&As[(a_r + st * 64) * A_STR + a_k4] = aReg[st];
        #pragma unroll
        for (int st = 0; st < 2; st++)
            *(float2*)&Ws[(w_c + st * 32) * W_STR + w_kp] = wReg[st];
        __syncthreads();

        #pragma unroll
        for (int p = 0; p < 16; p++) {    // kk-pair
            ull a[4], w[4];
            #pragma unroll
            for (int i = 0; i < 4; i++)
                a[i] = *(const ull*)&As[(row_slot + 32 * i) * A_STR + 2 * p];
            #pragma unroll
            for (int j = 0; j < 4; j++)
                w[j] = *(const ull*)&Ws[(col_t + 16 * j) * W_STR + 2 * p];
            #pragma unroll
            for (int i = 0; i < 4; i++)
                #pragma unroll
                for (int j = 0; j < 4; j++)
                    acc[i][j] = fma2(a[i], w[j], acc[i][j]);
        }
    }

    // Store 8-byte (even,odd) partial pairs; reduce kernel folds lo+hi.
    #pragma unroll
    for (int i = 0; i < 4; i++) {
        long r = row0 + row_slot + 32 * i;
        #pragma unroll
        for (int j = 0; j < 4; j++)
            Cp[r * VDIM + c0 + col_t + 16 * j] = acc[i][j];
    }
}

// ---------------------------------------------------------------------------
// Sum NS pair-partials (lo+hi), add bias to D, store exp() of the result.
// ---------------------------------------------------------------------------
__global__ __launch_bounds__(256) void reduce_exp(const float* __restrict__ bias)
{
    int idx = blockIdx.x * 256 + threadIdx.x;
    if (idx < 65536) {                 // E: 65536 float4 outputs
        const float4* p = (const float4*)g_Ep;
        float ax = 0.f, ay = 0.f, az = 0.f, aw = 0.f;
        #pragma unroll
        for (int s = 0; s < NS; s++) {
            float4 v0 = p[(long)s * 131072 + idx * 2];
            float4 v1 = p[(long)s * 131072 + idx * 2 + 1];
            ax += v0.x + v0.y; ay += v0.z + v0.w;
            az += v1.x + v1.y; aw += v1.z + v1.w;
        }
        ((float4*)g_E)[idx] = make_float4(__expf(ax), __expf(ay), __expf(az), __expf(aw));
    } else {                           // D: 16384 float4 outputs
        int j = idx - 65536;
        const float4* p = (const float4*)g_Dp;
        float4 bv = ((const float4*)bias)[j & 31];
        float ax = bv.x, ay = bv.y, az = bv.z, aw = bv.w;
        #pragma unroll
        for (int s = 0; s < NS; s++) {
            float4 v0 = p[(long)s * 32768 + j * 2];
            float4 v1 = p[(long)s * 32768 + j * 2 + 1];
            ax += v0.x + v0.y; ay += v0.z + v0.w;
            az += v1.x + v1.y; aw += v1.z + v1.w;
        }
        ((float4*)g_D)[j] = make_float4(__expf(ax), __expf(ay), __expf(az), __expf(aw));
    }
}

// ---------------------------------------------------------------------------
// Softmax: block covers 4 bt x 8 u (32 rows). Warp handles 4 rows sharing
// one E row; D rows L1-reused across the block's 4 t values.
// ---------------------------------------------------------------------------
__global__ __launch_bounds__(256) void softmax_kernel(float* __restrict__ out)
{
    const int warp = threadIdx.x >> 5;
    const int lane = threadIdx.x & 31;
    const int btg = blockIdx.x >> 3;          // 512 groups of 4 bt
    const int ug  = blockIdx.x & 7;           // 8 groups of 8 u
    const int bt  = btg * 4 + (warp >> 1);
    const int b   = bt >> 8;
    const int u0  = ug * 8 + (warp & 1) * 4;

    float4 ev = ((const float4*)g_E)[bt * 32 + lane];
    const float4* Dr = (const float4*)g_D + ((b << 6) + u0) * 32;

    float4 p[4];
    float  sum[4];
    #pragma unroll
    for (int k = 0; k < 4; k++) {
        float4 dv = Dr[k * 32 + lane];
        p[k].x = ev.x * dv.x; p[k].y = ev.y * dv.y;
        p[k].z = ev.z * dv.z; p[k].w = ev.w * dv.w;
        sum[k] = (p[k].x + p[k].y) + (p[k].z + p[k].w);
    }
    #pragma unroll
    for (int sh = 16; sh > 0; sh >>= 1) {
        #pragma unroll
        for (int k = 0; k < 4; k++)
            sum[k] += __shfl_xor_sync(0xffffffffu, sum[k], sh);
    }
    float4* o = (float4*)out + ((long)bt * 64 + u0) * 32;
    #pragma unroll
    for (int k = 0; k < 4; k++) {
        float inv = __fdividef(1.0f, sum[k]);
        o[k * 32 + lane] = make_float4(p[k].x * inv, p[k].y * inv,
                                       p[k].z * inv, p[k].w * inv);
    }
}

// ---------------------------------------------------------------------------
extern "C" void kernel_launch(void* const* d_in, const int* in_sizes, int n_in,
                              void* d_out, int out_size)
{
    const float* enc = (const float*)d_in[0];  // [8,256,1024]
    const float* dec = (const float*)d_in[1];  // [8,64,1024]
    const float* W   = (const float*)d_in[2];  // [128,1024]
    const float* b   = (const float*)d_in[3];  // [128]
    float* out = (float*)d_out;                // [8,256,64,128]

    joint_gemm<<<280, 512>>>(enc, dec, W);
    reduce_exp<<<320, 256>>>(b);
    softmax_kernel<<<4096, 256>>>(out);
}

// round 12
// speedup vs baseline: 1.2769x; 1.2769x over previous
#include <cuda_runtime.h>
#include <cstdint>

#define HDIM 1024
#define VDIM 128
#define NS   7          // K-splits: 3 chunks of 128 + 4 chunks of 160
#define NT   20         // row tiles: 16 enc + 4 dec, 128 rows each
#define STR  36         // smem row stride in 4B words (conflict-free frags)

// Split-K fp32 partials; reduced+exp'd results
__device__ __align__(16) float g_Ep[NS * 2048 * VDIM];   // 7.3 MB
__device__ __align__(16) float g_Dp[NS * 512 * VDIM];    // 1.8 MB
__device__ __align__(16) float g_E[2048 * VDIM];         // exp(enc@W^T)
__device__ __align__(16) float g_D[512 * VDIM];          // exp(dec@W^T + b)

__device__ __forceinline__ uint32_t f2tf32(float x) {
    uint32_t r;
    asm("cvt.rna.tf32.f32 %0, %1;" : "=r"(r) : "f"(x));
    return r;
}
__device__ __forceinline__ void mma_tf32(float* d, const uint32_t* a,
                                         const uint32_t* b) {
    asm volatile(
        "mma.sync.aligned.m16n8k8.row.col.f32.tf32.tf32.f32 "
        "{%0,%1,%2,%3}, {%4,%5,%6,%7}, {%8,%9}, {%0,%1,%2,%3};"
        : "+f"(d[0]), "+f"(d[1]), "+f"(d[2]), "+f"(d[3])
        : "r"(a[0]), "r"(a[1]), "r"(a[2]), "r"(a[3]), "r"(b[0]), "r"(b[1]));
}

#define SMEM_DYN (4 * 128 * STR * 4)   // Ah|Al|Wh|Wl = 73728 B

// ---------------------------------------------------------------------------
// 3xTF32 split-K GEMM on tensor cores (mma.sync, sm_80+ path -> HMMA).
// Grid 140 = 7 K-splits x 20 tiles, 256 thr, 1 CTA/SM.
// CTA tile 128x128, K-chunk 32. Warp tile 64x32 = 4x4 m16n8k8 mmas.
// 3 passes per k-step: Ah*Wh + Ah*Wl + Al*Wh, fp32 reg accumulators.
// ---------------------------------------------------------------------------
__global__ __launch_bounds__(256) void joint_gemm_mma(
    const float* __restrict__ enc, const float* __restrict__ dec,
    const float* __restrict__ Wt)
{
    extern __shared__ __align__(16) uint32_t sm[];
    uint32_t* Ah = sm;
    uint32_t* Al = sm + 128 * STR;
    uint32_t* Wh = sm + 2 * 128 * STR;
    uint32_t* Wl = sm + 3 * 128 * STR;

    const int s    = blockIdx.x / NT;
    const int tile = blockIdx.x - s * NT;
    const int nch  = (s < 3) ? 4 : 5;
    const int k_lo = (s < 3) ? s * 128 : 384 + (s - 3) * 160;

    const bool is_dec = (tile >= 16);
    const float* A = is_dec ? dec : enc;
    const int row0 = (is_dec ? tile - 16 : tile) * 128;
    float* Cp = is_dec ? (g_Dp + s * 512 * VDIM) : (g_Ep + s * 2048 * VDIM);

    const int tid  = threadIdx.x;
    const int lane = tid & 31;
    const int warp = tid >> 5;
    const int warpRow = (warp >> 2) * 64;   // 2 row groups of 64
    const int warpCol = (warp & 3) * 32;    // 4 col groups of 32
    const int lr = lane >> 2;               // 0..7
    const int lc = lane & 3;                // 0..3

    // staging map: 1024 float4 slots each for A and W, 4 per thread
    const int st_r  = tid >> 3;             // 0..31 (+32/step)
    const int st_k4 = (tid & 7) << 2;

    float acc[4][4][4];
    #pragma unroll
    for (int mi = 0; mi < 4; mi++)
        #pragma unroll
        for (int ni = 0; ni < 4; ni++)
            #pragma unroll
            for (int q = 0; q < 4; q++) acc[mi][ni][q] = 0.0f;

    for (int ck = 0; ck < nch; ck++) {
        const int k0 = k_lo + ck * 32;
        float4 av[4], wv[4];
        #pragma unroll
        for (int st = 0; st < 4; st++) {
            int r = st_r + st * 32;
            av[st] = *(const float4*)(A + (long)(row0 + r) * HDIM + k0 + st_k4);
            wv[st] = *(const float4*)(Wt + (long)r * HDIM + k0 + st_k4);
        }
        __syncthreads();                       // previous compute done
        #pragma unroll
        for (int st = 0; st < 4; st++) {
            int base = (st_r + st * 32) * STR + st_k4;
            const float* ap = (const float*)&av[st];
            const float* wp = (const float*)&wv[st];
            #pragma unroll
            for (int q = 0; q < 4; q++) {
                uint32_t h = f2tf32(ap[q]);
                Ah[base + q] = h;
                Al[base + q] = f2tf32(ap[q] - __uint_as_float(h));
                h = f2tf32(wp[q]);
                Wh[base + q] = h;
                Wl[base + q] = f2tf32(wp[q] - __uint_as_float(h));
            }
        }
        __syncthreads();

        #pragma unroll
        for (int ks = 0; ks < 4; ks++) {
            const int kk = ks * 8;
            uint32_t ah[4][4], al[4][4], wh[4][2], wl[4][2];
            #pragma unroll
            for (int mi = 0; mi < 4; mi++) {
                int rb = (warpRow + mi * 16 + lr) * STR + kk + lc;
                ah[mi][0] = Ah[rb];           al[mi][0] = Al[rb];
                ah[mi][1] = Ah[rb + 8 * STR]; al[mi][1] = Al[rb + 8 * STR];
                ah[mi][2] = Ah[rb + 4];       al[mi][2] = Al[rb + 4];
                ah[mi][3] = Ah[rb + 8 * STR + 4]; al[mi][3] = Al[rb + 8 * STR + 4];
            }
            #pragma unroll
            for (int ni = 0; ni < 4; ni++) {
                int nb = (warpCol + ni * 8 + lr) * STR + kk + lc;
                wh[ni][0] = Wh[nb];     wl[ni][0] = Wl[nb];
                wh[ni][1] = Wh[nb + 4]; wl[ni][1] = Wl[nb + 4];
            }
            #pragma unroll
            for (int mi = 0; mi < 4; mi++)
                #pragma unroll
                for (int ni = 0; ni < 4; ni++) {
                    mma_tf32(acc[mi][ni], al[mi], wh[ni]);  // low-order first
                    mma_tf32(acc[mi][ni], ah[mi], wl[ni]);
                    mma_tf32(acc[mi][ni], ah[mi], wh[ni]);
                }
        }
    }

    // Epilogue: c0,c1 adjacent cols -> float2 stores.
    #pragma unroll
    for (int mi = 0; mi < 4; mi++) {
        long r0g = row0 + warpRow + mi * 16 + lr;
        #pragma unroll
        for (int ni = 0; ni < 4; ni++) {
            int c = warpCol + ni * 8 + lc * 2;
            *(float2*)&Cp[r0g * VDIM + c] =
                make_float2(acc[mi][ni][0], acc[mi][ni][1]);
            *(float2*)&Cp[(r0g + 8) * VDIM + c] =
                make_float2(acc[mi][ni][2], acc[mi][ni][3]);
        }
    }
}

// ---------------------------------------------------------------------------
// Sum NS partials, add bias to D, store exp() of the result.
// ---------------------------------------------------------------------------
__global__ __launch_bounds__(256) void reduce_exp(const float* __restrict__ bias)
{
    int idx = blockIdx.x * 256 + threadIdx.x;
    if (idx < 65536) {                 // E: 65536 float4 outputs
        const float4* p = (const float4*)g_Ep;
        float4 a = p[idx];
        #pragma unroll
        for (int s = 1; s < NS; s++) {
            float4 v = p[idx + s * 65536];
            a.x += v.x; a.y += v.y; a.z += v.z; a.w += v.w;
        }
        ((float4*)g_E)[idx] = make_float4(__expf(a.x), __expf(a.y),
                                          __expf(a.z), __expf(a.w));
    } else {                           // D: 16384 float4 outputs
        int j = idx - 65536;
        const float4* p = (const float4*)g_Dp;
        float4 a = ((const float4*)bias)[j & 31];
        #pragma unroll
        for (int s = 0; s < NS; s++) {
            float4 v = p[j + s * 16384];
            a.x += v.x; a.y += v.y; a.z += v.z; a.w += v.w;
        }
        ((float4*)g_D)[j] = make_float4(__expf(a.x), __expf(a.y),
                                        __expf(a.z), __expf(a.w));
    }
}

// ---------------------------------------------------------------------------
// Softmax: block covers 4 bt x 8 u (32 rows). Warp handles 4 rows sharing
// one E row; D rows L1-reused across the block's 4 t values.
// ---------------------------------------------------------------------------
__global__ __launch_bounds__(256) void softmax_kernel(float* __restrict__ out)
{
    const int warp = threadIdx.x >> 5;
    const int lane = threadIdx.x & 31;
    const int btg = blockIdx.x >> 3;
    const int ug  = blockIdx.x & 7;
    const int bt  = btg * 4 + (warp >> 1);
    const int b   = bt >> 8;
    const int u0  = ug * 8 + (warp & 1) * 4;

    float4 ev = ((const float4*)g_E)[bt * 32 + lane];
    const float4* Dr = (const float4*)g_D + ((b << 6) + u0) * 32;

    float4 p[4];
    float  sum[4];
    #pragma unroll
    for (int k = 0; k < 4; k++) {
        float4 dv = Dr[k * 32 + lane];
        p[k].x = ev.x * dv.x; p[k].y = ev.y * dv.y;
        p[k].z = ev.z * dv.z; p[k].w = ev.w * dv.w;
        sum[k] = (p[k].x + p[k].y) + (p[k].z + p[k].w);
    }
    #pragma unroll
    for (int sh = 16; sh > 0; sh >>= 1) {
        #pragma unroll
        for (int k = 0; k < 4; k++)
            sum[k] += __shfl_xor_sync(0xffffffffu, sum[k], sh);
    }
    float4* o = (float4*)out + ((long)bt * 64 + u0) * 32;
    #pragma unroll
    for (int k = 0; k < 4; k++) {
        float inv = __fdividef(1.0f, sum[k]);
        o[k * 32 + lane] = make_float4(p[k].x * inv, p[k].y * inv,
                                       p[k].z * inv, p[k].w * inv);
    }
}

// ---------------------------------------------------------------------------
extern "C" void kernel_launch(void* const* d_in, const int* in_sizes, int n_in,
                              void* d_out, int out_size)
{
    const float* enc = (const float*)d_in[0];  // [8,256,1024]
    const float* dec = (const float*)d_in[1];  // [8,64,1024]
    const float* W   = (const float*)d_in[2];  // [128,1024]
    const float* b   = (const float*)d_in[3];  // [128]
    float* out = (float*)d_out;                // [8,256,64,128]

    static int smem_set = 0;
    if (!smem_set) {
        cudaFuncSetAttribute(joint_gemm_mma,
                             cudaFuncAttributeMaxDynamicSharedMemorySize, SMEM_DYN);
        smem_set = 1;
    }
    joint_gemm_mma<<<140, 256, SMEM_DYN>>>(enc, dec, W);
    reduce_exp<<<320, 256>>>(b);
    softmax_kernel<<<4096, 256>>>(out);
}

// round 13
// speedup vs baseline: 1.3018x; 1.0195x over previous
#include <cuda_runtime.h>
#include <cstdint>

#define HDIM 1024
#define VDIM 128
#define NS   7          // K-splits: 3 chunks of 128 + 4 chunks of 160
#define NT   40         // 20 row-tiles x 2 col-halves
#define STR  36         // smem row stride in 4B words (conflict-free frags)

// Split-K fp32 partials; reduced+exp'd results
__device__ __align__(16) float g_Ep[NS * 2048 * VDIM];   // 7.3 MB
__device__ __align__(16) float g_Dp[NS * 512 * VDIM];    // 1.8 MB
__device__ __align__(16) float g_E[2048 * VDIM];         // exp(enc@W^T)
__device__ __align__(16) float g_D[512 * VDIM];          // exp(dec@W^T + b)

__device__ __forceinline__ uint32_t f2tf32(float x) {
    uint32_t r;
    asm("cvt.rna.tf32.f32 %0, %1;" : "=r"(r) : "f"(x));
    return r;
}
__device__ __forceinline__ void mma_tf32(float* d, const uint32_t* a,
                                         const uint32_t* b) {
    asm volatile(
        "mma.sync.aligned.m16n8k8.row.col.f32.tf32.tf32.f32 "
        "{%0,%1,%2,%3}, {%4,%5,%6,%7}, {%8,%9}, {%0,%1,%2,%3};"
        : "+f"(d[0]), "+f"(d[1]), "+f"(d[2]), "+f"(d[3])
        : "r"(a[0]), "r"(a[1]), "r"(a[2]), "r"(a[3]), "r"(b[0]), "r"(b[1]));
}

#define A_WORDS (128 * STR)
#define W_WORDS (64 * STR)
#define SMEM_DYN ((2 * A_WORDS + 2 * W_WORDS) * 4)   // 55296 B

// ---------------------------------------------------------------------------
// 3xTF32 split-K GEMM on tensor cores (mma.sync -> HMMA).
// Grid 280 = 7 K-splits x 40 tiles (20 row x 2 col-halves); 2 CTAs/SM.
// CTA tile 128 rows x 64 cols, K-chunk 32. Warp tile 32x32 = 2x4 m16n8k8.
// 3 passes per k-step: Al*Wh + Ah*Wl + Ah*Wh, fp32 reg accumulators.
// Two co-resident CTAs interleave staging and MMA phases -> latency hiding.
// ---------------------------------------------------------------------------
__global__ __launch_bounds__(256, 2) void joint_gemm_mma(
    const float* __restrict__ enc, const float* __restrict__ dec,
    const float* __restrict__ Wt)
{
    extern __shared__ __align__(16) uint32_t sm[];
    uint32_t* Ah = sm;
    uint32_t* Al = sm + A_WORDS;
    uint32_t* Wh = sm + 2 * A_WORDS;
    uint32_t* Wl = sm + 2 * A_WORDS + W_WORDS;

    const int s    = blockIdx.x / NT;
    const int tile = blockIdx.x - s * NT;
    const int nch  = (s < 3) ? 4 : 5;
    const int k_lo = (s < 3) ? s * 128 : 384 + (s - 3) * 160;

    const int rt = tile >> 1, ch = tile & 1;
    const bool is_dec = (rt >= 16);
    const float* A = is_dec ? dec : enc;
    const int row0 = (is_dec ? rt - 16 : rt) * 128;
    const int c0   = ch * 64;
    float* Cp = is_dec ? (g_Dp + s * 512 * VDIM) : (g_Ep + s * 2048 * VDIM);

    const int tid  = threadIdx.x;
    const int lane = tid & 31;
    const int warp = tid >> 5;
    const int warpRow = (warp >> 1) * 32;   // 4 row groups of 32
    const int warpCol = (warp & 1) * 32;    // 2 col groups of 32
    const int lr = lane >> 2;               // 0..7
    const int lc = lane & 3;                // 0..3

    // Staging: A = 1024 float4 slots (4/thread), W = 512 float4 slots (2/thread)
    const int a_r  = tid >> 3;              // 0..31 (+32/step)
    const int a_k4 = (tid & 7) << 2;
    const int w_r  = tid >> 3;              // 0..31 (+32 second step)
    const int w_k4 = (tid & 7) << 2;

    float acc[2][4][4];
    #pragma unroll
    for (int mi = 0; mi < 2; mi++)
        #pragma unroll
        for (int ni = 0; ni < 4; ni++)
            #pragma unroll
            for (int q = 0; q < 4; q++) acc[mi][ni][q] = 0.0f;

    for (int ck = 0; ck < nch; ck++) {
        const int k0 = k_lo + ck * 32;
        float4 av[4], wv[2];
        #pragma unroll
        for (int st = 0; st < 4; st++)
            av[st] = *(const float4*)(A + (long)(row0 + a_r + st * 32) * HDIM + k0 + a_k4);
        #pragma unroll
        for (int st = 0; st < 2; st++)
            wv[st] = *(const float4*)(Wt + (long)(c0 + w_r + st * 32) * HDIM + k0 + w_k4);

        __syncthreads();                       // previous compute done
        #pragma unroll
        for (int st = 0; st < 4; st++) {
            int base = (a_r + st * 32) * STR + a_k4;
            const float* ap = (const float*)&av[st];
            #pragma unroll
            for (int q = 0; q < 4; q++) {
                uint32_t h = f2tf32(ap[q]);
                Ah[base + q] = h;
                Al[base + q] = f2tf32(ap[q] - __uint_as_float(h));
            }
        }
        #pragma unroll
        for (int st = 0; st < 2; st++) {
            int base = (w_r + st * 32) * STR + w_k4;
            const float* wp = (const float*)&wv[st];
            #pragma unroll
            for (int q = 0; q < 4; q++) {
                uint32_t h = f2tf32(wp[q]);
                Wh[base + q] = h;
                Wl[base + q] = f2tf32(wp[q] - __uint_as_float(h));
            }
        }
        __syncthreads();

        #pragma unroll
        for (int ks = 0; ks < 4; ks++) {
            const int kk = ks * 8;
            uint32_t ah[2][4], al[2][4], wh[4][2], wl[4][2];
            #pragma unroll
            for (int mi = 0; mi < 2; mi++) {
                int rb = (warpRow + mi * 16 + lr) * STR + kk + lc;
                ah[mi][0] = Ah[rb];               al[mi][0] = Al[rb];
                ah[mi][1] = Ah[rb + 8 * STR];     al[mi][1] = Al[rb + 8 * STR];
                ah[mi][2] = Ah[rb + 4];           al[mi][2] = Al[rb + 4];
                ah[mi][3] = Ah[rb + 8 * STR + 4]; al[mi][3] = Al[rb + 8 * STR + 4];
            }
            #pragma unroll
            for (int ni = 0; ni < 4; ni++) {
                int nb = (warpCol + ni * 8 + lr) * STR + kk + lc;
                wh[ni][0] = Wh[nb];     wl[ni][0] = Wl[nb];
                wh[ni][1] = Wh[nb + 4]; wl[ni][1] = Wl[nb + 4];
            }
            #pragma unroll
            for (int mi = 0; mi < 2; mi++)
                #pragma unroll
                for (int ni = 0; ni < 4; ni++) {
                    mma_tf32(acc[mi][ni], al[mi], wh[ni]);  // low-order first
                    mma_tf32(acc[mi][ni], ah[mi], wl[ni]);
                    mma_tf32(acc[mi][ni], ah[mi], wh[ni]);
                }
        }
    }

    // Epilogue: (c, c+1) adjacent -> float2 stores.
    #pragma unroll
    for (int mi = 0; mi < 2; mi++) {
        long rg = row0 + warpRow + mi * 16 + lr;
        #pragma unroll
        for (int ni = 0; ni < 4; ni++) {
            int c = c0 + warpCol + ni * 8 + lc * 2;
            *(float2*)&Cp[rg * VDIM + c] =
                make_float2(acc[mi][ni][0], acc[mi][ni][1]);
            *(float2*)&Cp[(rg + 8) * VDIM + c] =
                make_float2(acc[mi][ni][2], acc[mi][ni][3]);
        }
    }
}

// ---------------------------------------------------------------------------
// Sum NS partials, add bias to D, store exp() of the result.
// ---------------------------------------------------------------------------
__global__ __launch_bounds__(256) void reduce_exp(const float* __restrict__ bias)
{
    int idx = blockIdx.x * 256 + threadIdx.x;
    if (idx < 65536) {                 // E: 65536 float4 outputs
        const float4* p = (const float4*)g_Ep;
        float4 a = p[idx];
        #pragma unroll
        for (int s = 1; s < NS; s++) {
            float4 v = p[idx + s * 65536];
            a.x += v.x; a.y += v.y; a.z += v.z; a.w += v.w;
        }
        ((float4*)g_E)[idx] = make_float4(__expf(a.x), __expf(a.y),
                                          __expf(a.z), __expf(a.w));
    } else {                           // D: 16384 float4 outputs
        int j = idx - 65536;
        const float4* p = (const float4*)g_Dp;
        float4 a = ((const float4*)bias)[j & 31];
        #pragma unroll
        for (int s = 0; s < NS; s++) {
            float4 v = p[j + s * 16384];
            a.x += v.x; a.y += v.y; a.z += v.z; a.w += v.w;
        }
        ((float4*)g_D)[j] = make_float4(__expf(a.x), __expf(a.y),
                                        __expf(a.z), __expf(a.w));
    }
}

// ---------------------------------------------------------------------------
// Softmax: block covers 4 bt x 8 u (32 rows). Warp handles 4 rows sharing
// one E row; D rows L1-reused across the block's 4 t values.
// ---------------------------------------------------------------------------
__global__ __launch_bounds__(256) void softmax_kernel(float* __restrict__ out)
{
    const int warp = threadIdx.x >> 5;
    const int lane = threadIdx.x & 31;
    const int btg = blockIdx.x >> 3;
    const int ug  = blockIdx.x & 7;
    const int bt  = btg * 4 + (warp >> 1);
    const int b   = bt >> 8;
    const int u0  = ug * 8 + (warp & 1) * 4;

    float4 ev = ((const float4*)g_E)[bt * 32 + lane];
    const float4* Dr = (const float4*)g_D + ((b << 6) + u0) * 32;

    float4 p[4];
    float  sum[4];
    #pragma unroll
    for (int k = 0; k < 4; k++) {
        float4 dv = Dr[k * 32 + lane];
        p[k].x = ev.x * dv.x; p[k].y = ev.y * dv.y;
        p[k].z = ev.z * dv.z; p[k].w = ev.w * dv.w;
        sum[k] = (p[k].x + p[k].y) + (p[k].z + p[k].w);
    }
    #pragma unroll
    for (int sh = 16; sh > 0; sh >>= 1) {
        #pragma unroll
        for (int k = 0; k < 4; k++)
            sum[k] += __shfl_xor_sync(0xffffffffu, sum[k], sh);
    }
    float4* o = (float4*)out + ((long)bt * 64 + u0) * 32;
    #pragma unroll
    for (int k = 0; k < 4; k++) {
        float inv = __fdividef(1.0f, sum[k]);
        o[k * 32 + lane] = make_float4(p[k].x * inv, p[k].y * inv,
                                       p[k].z * inv, p[k].w * inv);
    }
}

// ---------------------------------------------------------------------------
extern "C" void kernel_launch(void* const* d_in, const int* in_sizes, int n_in,
                              void* d_out, int out_size)
{
    const float* enc = (const float*)d_in[0];  // [8,256,1024]
    const float* dec = (const float*)d_in[1];  // [8,64,1024]
    const float* W   = (const float*)d_in[2];  // [128,1024]
    const float* b   = (const float*)d_in[3];  // [128]
    float* out = (float*)d_out;                // [8,256,64,128]

    static int smem_set = 0;
    if (!smem_set) {
        cudaFuncSetAttribute(joint_gemm_mma,
                             cudaFuncAttributeMaxDynamicSharedMemorySize, SMEM_DYN);
        smem_set = 1;
    }
    joint_gemm_mma<<<280, 256, SMEM_DYN>>>(enc, dec, W);
    reduce_exp<<<320, 256>>>(b);
    softmax_kernel<<<4096, 256>>>(out);
}

// round 14
// speedup vs baseline: 1.3041x; 1.0018x over previous
#include <cuda_runtime.h>
#include <cstdint>

#define HDIM 1024
#define VDIM 128
#define NS   7          // K-splits: 3 chunks of 128 + 4 chunks of 160
#define NT   40         // 20 row-tiles x 2 col-halves
#define STR  36         // smem row stride in 4B words (conflict-free frags)

// Split-K fp32 partials; reduced+exp'd results
__device__ __align__(16) float g_Ep[NS * 2048 * VDIM];   // 7.3 MB
__device__ __align__(16) float g_Dp[NS * 512 * VDIM];    // 1.8 MB
__device__ __align__(16) float g_E[2048 * VDIM];         // exp(enc@W^T)
__device__ __align__(16) float g_D[512 * VDIM];          // exp(dec@W^T + b)

__device__ __forceinline__ uint32_t f2tf32(float x) {
    uint32_t r;
    asm("cvt.rna.tf32.f32 %0, %1;" : "=r"(r) : "f"(x));
    return r;
}
__device__ __forceinline__ void mma_tf32(float* d, const uint32_t* a,
                                         const uint32_t* b) {
    asm volatile(
        "mma.sync.aligned.m16n8k8.row.col.f32.tf32.tf32.f32 "
        "{%0,%1,%2,%3}, {%4,%5,%6,%7}, {%8,%9}, {%0,%1,%2,%3};"
        : "+f"(d[0]), "+f"(d[1]), "+f"(d[2]), "+f"(d[3])
        : "r"(a[0]), "r"(a[1]), "r"(a[2]), "r"(a[3]), "r"(b[0]), "r"(b[1]));
}

#define A_WORDS (128 * STR)
#define W_WORDS (64 * STR)
#define SMEM_DYN ((2 * A_WORDS + 2 * W_WORDS) * 4)   // 55296 B

// ---------------------------------------------------------------------------
// 3xTF32 split-K GEMM on tensor cores (mma.sync -> HMMA).
// Grid 280 = 7 K-splits x 40 tiles (20 row x 2 col-halves); 2 CTAs/SM.
// CTA tile 128 rows x 64 cols, K-chunk 32. Warp tile 32x32 = 2x4 m16n8k8.
// KEY CHANGE vs r13: the 3 precision passes are the OUTER loop per k-step,
// so consecutive HMMAs target 8 independent accumulators (RAW distance 8)
// instead of chaining 3-deep into one acc (RAW distance 1).
// ---------------------------------------------------------------------------
__global__ __launch_bounds__(256, 2) void joint_gemm_mma(
    const float* __restrict__ enc, const float* __restrict__ dec,
    const float* __restrict__ Wt)
{
    extern __shared__ __align__(16) uint32_t sm[];
    uint32_t* Ah = sm;
    uint32_t* Al = sm + A_WORDS;
    uint32_t* Wh = sm + 2 * A_WORDS;
    uint32_t* Wl = sm + 2 * A_WORDS + W_WORDS;

    const int s    = blockIdx.x / NT;
    const int tile = blockIdx.x - s * NT;
    const int nch  = (s < 3) ? 4 : 5;
    const int k_lo = (s < 3) ? s * 128 : 384 + (s - 3) * 160;

    const int rt = tile >> 1, ch = tile & 1;
    const bool is_dec = (rt >= 16);
    const float* A = is_dec ? dec : enc;
    const int row0 = (is_dec ? rt - 16 : rt) * 128;
    const int c0   = ch * 64;
    float* Cp = is_dec ? (g_Dp + s * 512 * VDIM) : (g_Ep + s * 2048 * VDIM);

    const int tid  = threadIdx.x;
    const int lane = tid & 31;
    const int warp = tid >> 5;
    const int warpRow = (warp >> 1) * 32;   // 4 row groups of 32
    const int warpCol = (warp & 1) * 32;    // 2 col groups of 32
    const int lr = lane >> 2;               // 0..7
    const int lc = lane & 3;                // 0..3

    // Staging: A = 1024 float4 slots (4/thread), W = 512 float4 slots (2/thread)
    const int a_r  = tid >> 3;              // 0..31 (+32/step)
    const int a_k4 = (tid & 7) << 2;

    float acc[2][4][4];
    #pragma unroll
    for (int mi = 0; mi < 2; mi++)
        #pragma unroll
        for (int ni = 0; ni < 4; ni++)
            #pragma unroll
            for (int q = 0; q < 4; q++) acc[mi][ni][q] = 0.0f;

    for (int ck = 0; ck < nch; ck++) {
        const int k0 = k_lo + ck * 32;
        float4 av[4], wv[2];
        #pragma unroll
        for (int st = 0; st < 4; st++)
            av[st] = *(const float4*)(A + (long)(row0 + a_r + st * 32) * HDIM + k0 + a_k4);
        #pragma unroll
        for (int st = 0; st < 2; st++)
            wv[st] = *(const float4*)(Wt + (long)(c0 + a_r + st * 32) * HDIM + k0 + a_k4);

        __syncthreads();                       // previous compute done
        #pragma unroll
        for (int st = 0; st < 4; st++) {
            int base = (a_r + st * 32) * STR + a_k4;
            const float* ap = (const float*)&av[st];
            #pragma unroll
            for (int q = 0; q < 4; q++) {
                uint32_t h = f2tf32(ap[q]);
                Ah[base + q] = h;
                Al[base + q] = f2tf32(ap[q] - __uint_as_float(h));
            }
        }
        #pragma unroll
        for (int st = 0; st < 2; st++) {
            int base = (a_r + st * 32) * STR + a_k4;
            const float* wp = (const float*)&wv[st];
            #pragma unroll
            for (int q = 0; q < 4; q++) {
                uint32_t h = f2tf32(wp[q]);
                Wh[base + q] = h;
                Wl[base + q] = f2tf32(wp[q] - __uint_as_float(h));
            }
        }
        __syncthreads();

        #pragma unroll
        for (int ks = 0; ks < 4; ks++) {
            const int kk = ks * 8;
            uint32_t ah[2][4], al[2][4], wh[4][2], wl[4][2];
            #pragma unroll
            for (int mi = 0; mi < 2; mi++) {
                int rb = (warpRow + mi * 16 + lr) * STR + kk + lc;
                ah[mi][0] = Ah[rb];               al[mi][0] = Al[rb];
                ah[mi][1] = Ah[rb + 8 * STR];     al[mi][1] = Al[rb + 8 * STR];
                ah[mi][2] = Ah[rb + 4];           al[mi][2] = Al[rb + 4];
                ah[mi][3] = Ah[rb + 8 * STR + 4]; al[mi][3] = Al[rb + 8 * STR + 4];
            }
            #pragma unroll
            for (int ni = 0; ni < 4; ni++) {
                int nb = (warpCol + ni * 8 + lr) * STR + kk + lc;
                wh[ni][0] = Wh[nb];     wl[ni][0] = Wl[nb];
                wh[ni][1] = Wh[nb + 4]; wl[ni][1] = Wl[nb + 4];
            }
            // Pass-major order: 8 independent accs between reuses of any acc.
            #pragma unroll
            for (int mi = 0; mi < 2; mi++)
                #pragma unroll
                for (int ni = 0; ni < 4; ni++)
                    mma_tf32(acc[mi][ni], al[mi], wh[ni]);   // low-order first
            #pragma unroll
            for (int mi = 0; mi < 2; mi++)
                #pragma unroll
                for (int ni = 0; ni < 4; ni++)
                    mma_tf32(acc[mi][ni], ah[mi], wl[ni]);
            #pragma unroll
            for (int mi = 0; mi < 2; mi++)
                #pragma unroll
                for (int ni = 0; ni < 4; ni++)
                    mma_tf32(acc[mi][ni], ah[mi], wh[ni]);
        }
    }

    // Epilogue: (c, c+1) adjacent -> float2 stores.
    #pragma unroll
    for (int mi = 0; mi < 2; mi++) {
        long rg = row0 + warpRow + mi * 16 + lr;
        #pragma unroll
        for (int ni = 0; ni < 4; ni++) {
            int c = c0 + warpCol + ni * 8 + lc * 2;
            *(float2*)&Cp[rg * VDIM + c] =
                make_float2(acc[mi][ni][0], acc[mi][ni][1]);
            *(float2*)&Cp[(rg + 8) * VDIM + c] =
                make_float2(acc[mi][ni][2], acc[mi][ni][3]);
        }
    }
}

// ---------------------------------------------------------------------------
// Sum NS partials, add bias to D, store exp() of the result.
// ---------------------------------------------------------------------------
__global__ __launch_bounds__(256) void reduce_exp(const float* __restrict__ bias)
{
    int idx = blockIdx.x * 256 + threadIdx.x;
    if (idx < 65536) {                 // E: 65536 float4 outputs
        const float4* p = (const float4*)g_Ep;
        float4 a = p[idx];
        #pragma unroll
        for (int s = 1; s < NS; s++) {
            float4 v = p[idx + s * 65536];
            a.x += v.x; a.y += v.y; a.z += v.z; a.w += v.w;
        }
        ((float4*)g_E)[idx] = make_float4(__expf(a.x), __expf(a.y),
                                          __expf(a.z), __expf(a.w));
    } else {                           // D: 16384 float4 outputs
        int j = idx - 65536;
        const float4* p = (const float4*)g_Dp;
        float4 a = ((const float4*)bias)[j & 31];
        #pragma unroll
        for (int s = 0; s < NS; s++) {
            float4 v = p[j + s * 16384];
            a.x += v.x; a.y += v.y; a.z += v.z; a.w += v.w;
        }
        ((float4*)g_D)[j] = make_float4(__expf(a.x), __expf(a.y),
                                        __expf(a.z), __expf(a.w));
    }
}

// ---------------------------------------------------------------------------
// Softmax: block covers 4 bt x 8 u (32 rows). Warp handles 4 rows sharing
// one E row; D rows L1-reused across the block's 4 t values.
// ---------------------------------------------------------------------------
__global__ __launch_bounds__(256) void softmax_kernel(float* __restrict__ out)
{
    const int warp = threadIdx.x >> 5;
    const int lane = threadIdx.x & 31;
    const int btg = blockIdx.x >> 3;
    const int ug  = blockIdx.x & 7;
    const int bt  = btg * 4 + (warp >> 1);
    const int b   = bt >> 8;
    const int u0  = ug * 8 + (warp & 1) * 4;

    float4 ev = ((const float4*)g_E)[bt * 32 + lane];
    const float4* Dr = (const float4*)g_D + ((b << 6) + u0) * 32;

    float4 p[4];
    float  sum[4];
    #pragma unroll
    for (int k = 0; k < 4; k++) {
        float4 dv = Dr[k * 32 + lane];
        p[k].x = ev.x * dv.x; p[k].y = ev.y * dv.y;
        p[k].z = ev.z * dv.z; p[k].w = ev.w * dv.w;
        sum[k] = (p[k].x + p[k].y) + (p[k].z + p[k].w);
    }
    #pragma unroll
    for (int sh = 16; sh > 0; sh >>= 1) {
        #pragma unroll
        for (int k = 0; k < 4; k++)
            sum[k] += __shfl_xor_sync(0xffffffffu, sum[k], sh);
    }
    float4* o = (float4*)out + ((long)bt * 64 + u0) * 32;
    #pragma unroll
    for (int k = 0; k < 4; k++) {
        float inv = __fdividef(1.0f, sum[k]);
        o[k * 32 + lane] = make_float4(p[k].x * inv, p[k].y * inv,
                                       p[k].z * inv, p[k].w * inv);
    }
}

// ---------------------------------------------------------------------------
extern "C" void kernel_launch(void* const* d_in, const int* in_sizes, int n_in,
                              void* d_out, int out_size)
{
    const float* enc = (const float*)d_in[0];  // [8,256,1024]
    const float* dec = (const float*)d_in[1];  // [8,64,1024]
    const float* W   = (const float*)d_in[2];  // [128,1024]
    const float* b   = (const float*)d_in[3];  // [128]
    float* out = (float*)d_out;                // [8,256,64,128]

    static int smem_set = 0;
    if (!smem_set) {
        cudaFuncSetAttribute(joint_gemm_mma,
                             cudaFuncAttributeMaxDynamicSharedMemorySize, SMEM_DYN);
        smem_set = 1;
    }
    joint_gemm_mma<<<280, 256, SMEM_DYN>>>(enc, dec, W);
    reduce_exp<<<320, 256>>>(b);
    softmax_kernel<<<4096, 256>>>(out);
}

// round 15
// speedup vs baseline: 1.3508x; 1.0358x over previous
#include <cuda_runtime.h>
#include <cstdint>

#define HDIM 1024
#define VDIM 128
#define NS   7          // K-splits: 3 chunks of 128 + 4 chunks of 160
#define NT   20         // row tiles: 16 enc + 4 dec, 128 rows each
#define STR  36         // smem row stride in 4B words (conflict-free frags)

// Split-K fp32 partials; reduced+exp'd results
__device__ __align__(16) float g_Ep[NS * 2048 * VDIM];   // 7.3 MB
__device__ __align__(16) float g_Dp[NS * 512 * VDIM];    // 1.8 MB
__device__ __align__(16) float g_E[2048 * VDIM];         // exp(enc@W^T)
__device__ __align__(16) float g_D[512 * VDIM];          // exp(dec@W^T + b)

__device__ __forceinline__ uint32_t f2tf32(float x) {
    uint32_t r;
    asm("cvt.rna.tf32.f32 %0, %1;" : "=r"(r) : "f"(x));
    return r;
}
__device__ __forceinline__ void mma_tf32(float* d, const uint32_t* a,
                                         const uint32_t* b) {
    asm volatile(
        "mma.sync.aligned.m16n8k8.row.col.f32.tf32.tf32.f32 "
        "{%0,%1,%2,%3}, {%4,%5,%6,%7}, {%8,%9}, {%0,%1,%2,%3};"
        : "+f"(d[0]), "+f"(d[1]), "+f"(d[2]), "+f"(d[3])
        : "r"(a[0]), "r"(a[1]), "r"(a[2]), "r"(a[3]), "r"(b[0]), "r"(b[1]));
}

#define TW (128 * STR)                 // words per sub-array
#define SMEM_DYN (2 * 4 * TW * 4)      // 2 bufs x (Ah|Al|Wh|Wl) = 147456 B

// ---------------------------------------------------------------------------
// 3xTF32 split-K GEMM, software-pipelined. Grid 140 = 7 K-splits x 20 tiles,
// 512 threads, 1 CTA/SM (smem-bound). CTA tile 128x128, K-chunk 32.
// Double-buffered smem: per iteration the warp does
//   cvt+STS(ck+1) -> LDG(ck+2) -> 96 MMAs(ck) -> one sync,
// so staging runs concurrently with tensor work instead of serializing.
// Warp tile 32x32 = 2x4 m16n8k8; pass-major order (8-deep acc independence).
// ---------------------------------------------------------------------------
__global__ __launch_bounds__(512) void joint_gemm_mma(
    const float* __restrict__ enc, const float* __restrict__ dec,
    const float* __restrict__ Wt)
{
    extern __shared__ __align__(16) uint32_t sm[];

    const int s    = blockIdx.x / NT;
    const int tile = blockIdx.x - s * NT;
    const int nch  = (s < 3) ? 4 : 5;
    const int k_lo = (s < 3) ? s * 128 : 384 + (s - 3) * 160;

    const bool is_dec = (tile >= 16);
    const float* A = is_dec ? dec : enc;
    const int row0 = (is_dec ? tile - 16 : tile) * 128;
    float* Cp = is_dec ? (g_Dp + s * 512 * VDIM) : (g_Ep + s * 2048 * VDIM);

    const int tid  = threadIdx.x;
    const int lane = tid & 31;
    const int warp = tid >> 5;              // 0..15
    const int warpRow = (warp >> 2) * 32;   // 4 row groups of 32
    const int warpCol = (warp & 3) * 32;    // 4 col groups of 32
    const int lr = lane >> 2;               // 0..7
    const int lc = lane & 3;                // 0..3

    // Staging map: A and W each 1024 float4 slots, 2 per thread.
    const int st_r  = tid >> 3;             // 0..63 (+64 second slot)
    const int st_k4 = (tid & 7) << 2;

    float4 avA[2], avW[2];                  // regs staged for chunk ck+1

    auto ldg = [&](int ck) {
        const int k0 = k_lo + ck * 32;
        avA[0] = *(const float4*)(A + (long)(row0 + st_r) * HDIM + k0 + st_k4);
        avA[1] = *(const float4*)(A + (long)(row0 + st_r + 64) * HDIM + k0 + st_k4);
        avW[0] = *(const float4*)(Wt + (long)st_r * HDIM + k0 + st_k4);
        avW[1] = *(const float4*)(Wt + (long)(st_r + 64) * HDIM + k0 + st_k4);
    };
    auto sts = [&](int ck) {                // cvt + store into buf[ck&1]
        uint32_t* Ah = sm + (ck & 1) * 4 * TW;
        uint32_t* Al = Ah + TW;
        uint32_t* Wh = Ah + 2 * TW;
        uint32_t* Wl = Ah + 3 * TW;
        #pragma unroll
        for (int st = 0; st < 2; st++) {
            int base = (st_r + st * 64) * STR + st_k4;
            const float* ap = (const float*)&avA[st];
            const float* wp = (const float*)&avW[st];
            #pragma unroll
            for (int q = 0; q < 4; q++) {
                uint32_t h = f2tf32(ap[q]);
                Ah[base + q] = h;
                Al[base + q] = f2tf32(ap[q] - __uint_as_float(h));
            }
            #pragma unroll
            for (int q = 0; q < 4; q++) {
                uint32_t h = f2tf32(wp[q]);
                Wh[base + q] = h;
                Wl[base + q] = f2tf32(wp[q] - __uint_as_float(h));
            }
        }
    };

    float acc[2][4][4];
    #pragma unroll
    for (int mi = 0; mi < 2; mi++)
        #pragma unroll
        for (int ni = 0; ni < 4; ni++)
            #pragma unroll
            for (int q = 0; q < 4; q++) acc[mi][ni][q] = 0.0f;

    // Prologue: fill buffer 0, preload chunk 1 into regs.
    ldg(0);
    sts(0);
    ldg(1);
    __syncthreads();

    for (int ck = 0; ck < nch; ck++) {
        const uint32_t* Ah = sm + (ck & 1) * 4 * TW;
        const uint32_t* Al = Ah + TW;
        const uint32_t* Wh = Ah + 2 * TW;
        const uint32_t* Wl = Ah + 3 * TW;

        // Stage next chunk into the other buffer (concurrent with MMAs below),
        // then refill regs for the chunk after that.
        if (ck + 1 < nch) sts(ck + 1);
        if (ck + 2 < nch) ldg(ck + 2);

        #pragma unroll
        for (int ks = 0; ks < 4; ks++) {
            const int kk = ks * 8;
            uint32_t ah[2][4], al[2][4], wh[4][2], wl[4][2];
            #pragma unroll
            for (int mi = 0; mi < 2; mi++) {
                int rb = (warpRow + mi * 16 + lr) * STR + kk + lc;
                ah[mi][0] = Ah[rb];               al[mi][0] = Al[rb];
                ah[mi][1] = Ah[rb + 8 * STR];     al[mi][1] = Al[rb + 8 * STR];
                ah[mi][2] = Ah[rb + 4];           al[mi][2] = Al[rb + 4];
                ah[mi][3] = Ah[rb + 8 * STR + 4]; al[mi][3] = Al[rb + 8 * STR + 4];
            }
            #pragma unroll
            for (int ni = 0; ni < 4; ni++) {
                int nb = (warpCol + ni * 8 + lr) * STR + kk + lc;
                wh[ni][0] = Wh[nb];     wl[ni][0] = Wl[nb];
                wh[ni][1] = Wh[nb + 4]; wl[ni][1] = Wl[nb + 4];
            }
            #pragma unroll
            for (int mi = 0; mi < 2; mi++)
                #pragma unroll
                for (int ni = 0; ni < 4; ni++)
                    mma_tf32(acc[mi][ni], al[mi], wh[ni]);   // low-order first
            #pragma unroll
            for (int mi = 0; mi < 2; mi++)
                #pragma unroll
                for (int ni = 0; ni < 4; ni++)
                    mma_tf32(acc[mi][ni], ah[mi], wl[ni]);
            #pragma unroll
            for (int mi = 0; mi < 2; mi++)
                #pragma unroll
                for (int ni = 0; ni < 4; ni++)
                    mma_tf32(acc[mi][ni], ah[mi], wh[ni]);
        }
        __syncthreads();
    }

    // Epilogue: (c, c+1) adjacent -> float2 stores.
    #pragma unroll
    for (int mi = 0; mi < 2; mi++) {
        long rg = row0 + warpRow + mi * 16 + lr;
        #pragma unroll
        for (int ni = 0; ni < 4; ni++) {
            int c = warpCol + ni * 8 + lc * 2;
            *(float2*)&Cp[rg * VDIM + c] =
                make_float2(acc[mi][ni][0], acc[mi][ni][1]);
            *(float2*)&Cp[(rg + 8) * VDIM + c] =
                make_float2(acc[mi][ni][2], acc[mi][ni][3]);
        }
    }
}

// ---------------------------------------------------------------------------
// Sum NS partials, add bias to D, store exp() of the result.
// ---------------------------------------------------------------------------
__global__ __launch_bounds__(256) void reduce_exp(const float* __restrict__ bias)
{
    int idx = blockIdx.x * 256 + threadIdx.x;
    if (idx < 65536) {                 // E: 65536 float4 outputs
        const float4* p = (const float4*)g_Ep;
        float4 a = p[idx];
        #pragma unroll
        for (int s = 1; s < NS; s++) {
            float4 v = p[idx + s * 65536];
            a.x += v.x; a.y += v.y; a.z += v.z; a.w += v.w;
        }
        ((float4*)g_E)[idx] = make_float4(__expf(a.x), __expf(a.y),
                                          __expf(a.z), __expf(a.w));
    } else {                           // D: 16384 float4 outputs
        int j = idx - 65536;
        const float4* p = (const float4*)g_Dp;
        float4 a = ((const float4*)bias)[j & 31];
        #pragma unroll
        for (int s = 0; s < NS; s++) {
            float4 v = p[j + s * 16384];
            a.x += v.x; a.y += v.y; a.z += v.z; a.w += v.w;
        }
        ((float4*)g_D)[j] = make_float4(__expf(a.x), __expf(a.y),
                                        __expf(a.z), __expf(a.w));
    }
}

// ---------------------------------------------------------------------------
// Softmax: block covers 4 bt x 8 u (32 rows). Warp handles 4 rows sharing
// one E row; D rows L1-reused across the block's 4 t values.
// ---------------------------------------------------------------------------
__global__ __launch_bounds__(256) void softmax_kernel(float* __restrict__ out)
{
    const int warp = threadIdx.x >> 5;
    const int lane = threadIdx.x & 31;
    const int btg = blockIdx.x >> 3;
    const int ug  = blockIdx.x & 7;
    const int bt  = btg * 4 + (warp >> 1);
    const int b   = bt >> 8;
    const int u0  = ug * 8 + (warp & 1) * 4;

    float4 ev = ((const float4*)g_E)[bt * 32 + lane];
    const float4* Dr = (const float4*)g_D + ((b << 6) + u0) * 32;

    float4 p[4];
    float  sum[4];
    #pragma unroll
    for (int k = 0; k < 4; k++) {
        float4 dv = Dr[k * 32 + lane];
        p[k].x = ev.x * dv.x; p[k].y = ev.y * dv.y;
        p[k].z = ev.z * dv.z; p[k].w = ev.w * dv.w;
        sum[k] = (p[k].x + p[k].y) + (p[k].z + p[k].w);
    }
    #pragma unroll
    for (int sh = 16; sh > 0; sh >>= 1) {
        #pragma unroll
        for (int k = 0; k < 4; k++)
            sum[k] += __shfl_xor_sync(0xffffffffu, sum[k], sh);
    }
    float4* o = (float4*)out + ((long)bt * 64 + u0) * 32;
    #pragma unroll
    for (int k = 0; k < 4; k++) {
        float inv = __fdividef(1.0f, sum[k]);
        o[k * 32 + lane] = make_float4(p[k].x * inv, p[k].y * inv,
                                       p[k].z * inv, p[k].w * inv);
    }
}

// ---------------------------------------------------------------------------
extern "C" void kernel_launch(void* const* d_in, const int* in_sizes, int n_in,
                              void* d_out, int out_size)
{
    const float* enc = (const float*)d_in[0];  // [8,256,1024]
    const float* dec = (const float*)d_in[1];  // [8,64,1024]
    const float* W   = (const float*)d_in[2];  // [128,1024]
    const float* b   = (const float*)d_in[3];  // [128]
    float* out = (float*)d_out;                // [8,256,64,128]

    static int smem_set = 0;
    if (!smem_set) {
        cudaFuncSetAttribute(joint_gemm_mma,
                             cudaFuncAttributeMaxDynamicSharedMemorySize, SMEM_DYN);
        smem_set = 1;
    }
    joint_gemm_mma<<<140, 512, SMEM_DYN>>>(enc, dec, W);
    reduce_exp<<<320, 256>>>(b);
    softmax_kernel<<<4096, 256>>>(out);
}